// round 15
// baseline (speedup 1.0000x reference)
#include <cuda_runtime.h>

#define Kn 6000
#define Np 3000
#define Mp 3000
#define F 256
#define H 4
#define HID 64
#define MAXNB 32
#define R2 0.0025f
#define SLOPE 0.2f

#define CELLS 20
#define NCELL (CELLS * CELLS * CELLS)
#define CSINV 19.8019801980198f   /* 1 / 0.0505 ; cell > max accepted pair dist */
#define CAP 16                    /* slots per cell; P(overflow) < 1e-12 at lambda=0.75 */

#define FNODES 8                  /* nodes per feat1 block */

// ---- device scratch (no dynamic allocation allowed) ----
__device__ float4 g_pts[Kn];
__device__ int    g_cellcnt[NCELL];
__device__ int    g_slots[NCELL * CAP];
__device__ float  g_w1as[H * 3];   // per-head W1^T @ asrc1  (3-vectors)
__device__ float  g_w1ad[H * 3];   // per-head W1^T @ adst1
__device__ int    g_nbr[Kn * MAXNB];
__device__ int    g_cnt[Kn];
__device__ float  g_h[Kn * F];
__device__ float  g_x[Kn * F];
__device__ float  g_es[Kn * H];
__device__ float  g_ed[Kn * H];

// ---- packed f32x2 helpers (bit-identical rn fp32 per lane, 2x FMA pipe) ----
__device__ __forceinline__ unsigned long long pack2(float lo, float hi) {
    unsigned long long r;
    asm("mov.b64 %0, {%1, %2};" : "=l"(r) : "f"(lo), "f"(hi));
    return r;
}
__device__ __forceinline__ void unpack2(unsigned long long v, float& lo, float& hi) {
    asm("mov.b64 {%0, %1}, %2;" : "=f"(lo), "=f"(hi) : "l"(v));
}
__device__ __forceinline__ void ffma2(unsigned long long& acc,
                                      unsigned long long a, unsigned long long b) {
    asm("fma.rn.f32x2 %0, %1, %2, %0;" : "+l"(acc) : "l"(a), "l"(b));
}
__device__ __forceinline__ void fadd2(unsigned long long& acc, unsigned long long o) {
    asm("add.rn.f32x2 %0, %0, %1;" : "+l"(acc) : "l"(o));
}

// ---------------------------------------------------------------------------
// 1. pack points, claim cell slots directly (no scan/scatter kernels).
//    Side job (block 0, 24 threads): per-head score 3-vectors W1^T @ a.
//    (g_cellcnt zeroed by a captured cudaMemsetAsync before this launch)
// ---------------------------------------------------------------------------
__global__ void build_pts(const float* __restrict__ pos,
                          const float* __restrict__ pnm,
                          const float* __restrict__ W1,
                          const float* __restrict__ asrc,
                          const float* __restrict__ adst) {
    if (blockIdx.x == 0 && threadIdx.x < 24) {
        int t = threadIdx.x;
        int sd = t & 1, d = (t >> 1) % 3, h = t / 6;
        const float* a = sd ? adst : asrc;
        float s = 0.f;
#pragma unroll 8
        for (int c = 0; c < HID; c++)
            s += W1[d * F + h * HID + c] * a[h * HID + c];
        (sd ? g_w1ad : g_w1as)[h * 3 + d] = s;
    }
    int i = blockIdx.x * blockDim.x + threadIdx.x;
    if (i >= Kn) return;
    float x, y, z;
    if (i < Np) { x = pos[i];     y = pos[Np + i];  z = pos[2 * Np + i]; }
    else        { int j = i - Np; x = pnm[j];       y = pnm[Mp + j];  z = pnm[2 * Mp + j]; }
    float sq = x * x + y * y + z * z;
    g_pts[i] = make_float4(x, y, z, sq);
    int cx = min(CELLS - 1, max(0, (int)(x * CSINV)));
    int cy = min(CELLS - 1, max(0, (int)(y * CSINV)));
    int cz = min(CELLS - 1, max(0, (int)(z * CSINV)));
    int cell = (cz * CELLS + cy) * CELLS + cx;
    int p = atomicAdd(&g_cellcnt[cell], 1);
    if (p < CAP) g_slots[cell * CAP + p] = i;
}

// ---------------------------------------------------------------------------
// 2. warp-per-node radius search, lane-per-cell: lane l owns neighbor cell l
//    (27 cells), loops its slots. Ballot-compacted hits, then rank-sorted
//    ascending (indices unique) -> identical edge list as the dense scan.
// ---------------------------------------------------------------------------
__global__ void nbr_search() {
    __shared__ int buf[4][MAXNB];
    int wslot = threadIdx.x >> 5;
    int lane  = threadIdx.x & 31;
    int i     = (blockIdx.x * blockDim.x + threadIdx.x) >> 5;
    if (i >= Kn) return;
    float4 pi = g_pts[i];
    int cx = min(CELLS - 1, max(0, (int)(pi.x * CSINV)));
    int cy = min(CELLS - 1, max(0, (int)(pi.y * CSINV)));
    int cz = min(CELLS - 1, max(0, (int)(pi.z * CSINV)));

    int cell = 0, cn = 0;
    if (lane < 27) {
        int dz = lane / 9 - 1, dy = (lane / 3) % 3 - 1, dx = lane % 3 - 1;
        int z = cz + dz, y = cy + dy, x = cx + dx;
        if ((unsigned)z < CELLS && (unsigned)y < CELLS && (unsigned)x < CELLS) {
            cell = (z * CELLS + y) * CELLS + x;
            cn = min(g_cellcnt[cell], CAP);
        }
    }
    int maxr = cn;
#pragma unroll
    for (int off = 16; off; off >>= 1)
        maxr = max(maxr, __shfl_xor_sync(0xffffffffu, maxr, off));

    int* nb = buf[wslot];
    int cnt = 0;
    for (int r = 0; r < maxr; r++) {
        bool ok = false;
        int j = -1;
        if (r < cn) {
            j = g_slots[cell * CAP + r];
            float4 pj = g_pts[j];
            float dot = pi.x * pj.x + pi.y * pj.y + pi.z * pj.z;
            float d2  = (pi.w + pj.w) - 2.0f * dot;   // identical to reference
            ok = (d2 < R2);
        }
        unsigned m = __ballot_sync(0xffffffffu, ok);
        if (ok) {
            int p = cnt + __popc(m & ((1u << lane) - 1u));
            if (p < MAXNB) nb[p] = j;
        }
        cnt += __popc(m);
        if (cnt > MAXNB) cnt = MAXNB;
    }
    __syncwarp();
    // rank sort: indices unique -> rank = #{u < v} is a permutation
    int v = (lane < cnt) ? nb[lane] : 0x7fffffff;
    int rank = 0;
#pragma unroll
    for (int k = 0; k < 32; k++) {
        int u = __shfl_sync(0xffffffffu, v, k);
        rank += (u < v);
    }
    if (lane < cnt) g_nbr[i * MAXNB + rank] = v;
    if (lane == 0)  g_cnt[i] = cnt;
}

// ---------------------------------------------------------------------------
// 3. h1 = pts @ W1; scores via precomputed 3-vectors: es = p . (W1^T asrc).
//    No reductions, no barriers. FNODES nodes per block.
// ---------------------------------------------------------------------------
__global__ void feat1(const float* __restrict__ W1) {
    int c = threadIdx.x;
    float w0 = W1[c], w1 = W1[F + c], w2 = W1[2 * F + c];
    int i0 = blockIdx.x * FNODES;
#pragma unroll
    for (int n = 0; n < FNODES; n++) {
        int i = i0 + n;
        float4 p = g_pts[i];                      // broadcast load
        g_h[i * F + c] = p.x * w0 + p.y * w1 + p.z * w2;
    }
    if (c < 2 * FNODES * H) {                     // 64 threads: sd, node, head
        int sd = c >> 5, idx = c & 31;
        int n = idx >> 2, h = idx & 3;
        float4 p = g_pts[i0 + n];
        const float* wa = (sd ? g_w1ad : g_w1as) + h * 3;
        float e = p.x * wa[0] + p.y * wa[1] + p.z * wa[2];
        (sd ? g_ed : g_es)[(i0 + n) * H + h] = e;
    }
}

// ---------------------------------------------------------------------------
// 4. sparse GAT softmax + aggregation; warp per node.
//    FINAL: only rows [Np, Kn) are ever used -> fuse fc and skip the rest.
// ---------------------------------------------------------------------------
template<bool FINAL>
__global__ void aggregate(const float* __restrict__ bias,
                          const float* __restrict__ fw,
                          const float* __restrict__ fb,
                          float* __restrict__ out) {
    int wi   = (blockIdx.x * blockDim.x + threadIdx.x) >> 5;
    int lane = threadIdx.x & 31;
    if (wi >= (FINAL ? Mp : Kn)) return;
    int node = FINAL ? (Np + wi) : wi;
    int cnt  = g_cnt[node];

    float e[H];
    int nb = 0;
    if (lane < cnt) {
        nb = g_nbr[node * MAXNB + lane];
#pragma unroll
        for (int h = 0; h < H; h++) {
            float v = g_ed[node * H + h] + g_es[nb * H + h];
            e[h] = (v >= 0.f) ? v : SLOPE * v;
        }
    } else {
#pragma unroll
        for (int h = 0; h < H; h++) e[h] = -1e30f;
    }

    float alpha[H];
#pragma unroll
    for (int h = 0; h < H; h++) {
        float m = e[h];
#pragma unroll
        for (int off = 16; off; off >>= 1)
            m = fmaxf(m, __shfl_xor_sync(0xffffffffu, m, off));
        float a = (lane < cnt) ? expf(e[h] - m) : 0.f;
        float s = a;
#pragma unroll
        for (int off = 16; off; off >>= 1)
            s += __shfl_xor_sync(0xffffffffu, s, off);
        alpha[h] = a / s;
    }

    float acc[8] = {0.f, 0.f, 0.f, 0.f, 0.f, 0.f, 0.f, 0.f};
    for (int j = 0; j < cnt; j++) {
        int   nj = __shfl_sync(0xffffffffu, nb, j);
        float aw[H];
#pragma unroll
        for (int h = 0; h < H; h++) aw[h] = __shfl_sync(0xffffffffu, alpha[h], j);
        const float* hr = g_h + nj * F;
#pragma unroll
        for (int r = 0; r < 8; r++)
            acc[r] += aw[r >> 1] * hr[lane + 32 * r];
    }

    float f0 = 0.f, f1 = 0.f;
#pragma unroll
    for (int r = 0; r < 8; r++) {
        int c = lane + 32 * r;
        float v = acc[r] + bias[c];
        v = (v > 0.f) ? v : 0.f;
        if (!FINAL) {
            g_x[node * F + c] = v;
        } else {
            f0 += v * fw[c * 2];
            f1 += v * fw[c * 2 + 1];
        }
    }
    if (FINAL) {
#pragma unroll
        for (int off = 16; off; off >>= 1) {
            f0 += __shfl_xor_sync(0xffffffffu, f0, off);
            f1 += __shfl_xor_sync(0xffffffffu, f1, off);
        }
        if (lane == 0) {
            out[wi * 2]     = f0 + fb[0];
            out[wi * 2 + 1] = f1 + fb[1];
        }
    }
}

// ---------------------------------------------------------------------------
// 5. h2 = x1 @ W2 — BM=64 x BN=64, 256 threads, SPLIT-K=2 (R13, kept).
// ---------------------------------------------------------------------------
#define BM 64
#define BN 64
#define BKT 32
__global__ void __launch_bounds__(256) gemm2(const float* __restrict__ W,
                                             const float* __restrict__ asrc,
                                             const float* __restrict__ adst) {
    __shared__ __align__(16) float smem_buf[BKT * BM + BKT * BN];  // 16 KB
    float* As = smem_buf;                 // As[k][m] = As[k*BM+m], transposed
    float* Bs = smem_buf + BKT * BM;      // Bs[k][n] = Bs[k*BN+n]
    int tid = threadIdx.x;
    int kg = tid >> 7;                    // split-K group: 0 or 1
    int wg_tid = tid & 127;
    int row0 = blockIdx.y * BM, col0 = blockIdx.x * BN;
    int tx = wg_tid & 15, ty = wg_tid >> 4;   // tx: n-quad, ty: m-group of 8
    unsigned long long acc[4][4];             // acc[mpair][n]
#pragma unroll
    for (int mp = 0; mp < 4; mp++)
#pragma unroll
        for (int n = 0; n < 4; n++) acc[mp][n] = 0ull;

    for (int kk = 0; kk < F; kk += BKT) {
#pragma unroll
        for (int it = 0; it < 2; it++) {
            int idx = tid + it * 256;
            int m = idx & 63, q = idx >> 6;       // q in 0..7
            int gr = row0 + m;
            float4 v = make_float4(0.f, 0.f, 0.f, 0.f);
            if (gr < Kn) v = *(const float4*)&g_x[gr * F + kk + q * 4];
            As[(q * 4 + 0) * BM + m] = v.x; As[(q * 4 + 1) * BM + m] = v.y;
            As[(q * 4 + 2) * BM + m] = v.z; As[(q * 4 + 3) * BM + m] = v.w;
        }
#pragma unroll
        for (int it = 0; it < 2; it++) {
            int idx = tid + it * 256;
            int k = idx >> 4, n4 = idx & 15;
            *(float4*)&Bs[k * BN + n4 * 4] =
                *(const float4*)&W[(kk + k) * F + col0 + n4 * 4];
        }
        __syncthreads();
#pragma unroll
        for (int k = 0; k < 16; k++) {
            int ks = kg * 16 + k;                 // this group's k within tile
            float4 b = *(const float4*)&Bs[ks * BN + tx * 4];
            unsigned long long bd[4];
            bd[0] = pack2(b.x, b.x); bd[1] = pack2(b.y, b.y);
            bd[2] = pack2(b.z, b.z); bd[3] = pack2(b.w, b.w);
            float4 a0 = *(const float4*)&As[ks * BM + ty * 8];
            float4 a1 = *(const float4*)&As[ks * BM + ty * 8 + 4];
            unsigned long long ap[4];
            ap[0] = pack2(a0.x, a0.y); ap[1] = pack2(a0.z, a0.w);
            ap[2] = pack2(a1.x, a1.y); ap[3] = pack2(a1.z, a1.w);
#pragma unroll
            for (int mp = 0; mp < 4; mp++)
#pragma unroll
                for (int n = 0; n < 4; n++) ffma2(acc[mp][n], ap[mp], bd[n]);
        }
        __syncthreads();
    }

    // split-K reduction: group1 -> smem, group0 adds (fixed order, deterministic)
    unsigned long long* red = (unsigned long long*)smem_buf;
    if (kg == 1) {
#pragma unroll
        for (int idx = 0; idx < 16; idx++)
            red[idx * 128 + wg_tid] = acc[idx >> 2][idx & 3];
    }
    __syncthreads();
    if (kg != 0) return;
#pragma unroll
    for (int idx = 0; idx < 16; idx++)
        fadd2(acc[idx >> 2][idx & 3], red[idx * 128 + wg_tid]);

    // epilogue (group0 only): unpack, store h2, fused es/ed for this head
    float as_[4], ad_[4];
#pragma unroll
    for (int n = 0; n < 4; n++) {
        as_[n] = asrc[col0 + tx * 4 + n];
        ad_[n] = adst[col0 + tx * 4 + n];
    }
    int hidx = col0 >> 6;
#pragma unroll
    for (int mp = 0; mp < 4; mp++) {
        float c0[4], c1[4];
#pragma unroll
        for (int n = 0; n < 4; n++) unpack2(acc[mp][n], c0[n], c1[n]);
#pragma unroll
        for (int half = 0; half < 2; half++) {
            float* c = half ? c1 : c0;
            int gr = row0 + ty * 8 + mp * 2 + half;
            float s = c[0] * as_[0] + c[1] * as_[1] + c[2] * as_[2] + c[3] * as_[3];
            float d = c[0] * ad_[0] + c[1] * ad_[1] + c[2] * ad_[2] + c[3] * ad_[3];
#pragma unroll
            for (int off = 8; off; off >>= 1) {
                s += __shfl_xor_sync(0xffffffffu, s, off);
                d += __shfl_xor_sync(0xffffffffu, d, off);
            }
            if (gr < Kn) {
                *(float4*)&g_h[gr * F + col0 + tx * 4] =
                    make_float4(c[0], c[1], c[2], c[3]);
                if (tx == 0) {
                    g_es[gr * H + hidx] = s;
                    g_ed[gr * H + hidx] = d;
                }
            }
        }
    }
}

// ---------------------------------------------------------------------------
extern "C" void kernel_launch(void* const* d_in, const int* in_sizes, int n_in,
                              void* d_out, int out_size) {
    const float* pos   = (const float*)d_in[0];
    const float* pnm   = (const float*)d_in[1];
    const float* W1    = (const float*)d_in[2];
    const float* asrc1 = (const float*)d_in[3];
    const float* adst1 = (const float*)d_in[4];
    const float* b1    = (const float*)d_in[5];
    const float* W2    = (const float*)d_in[6];
    const float* asrc2 = (const float*)d_in[7];
    const float* adst2 = (const float*)d_in[8];
    const float* b2    = (const float*)d_in[9];
    const float* fw    = (const float*)d_in[10];
    const float* fb    = (const float*)d_in[11];
    float* out = (float*)d_out;

    // zero the cell counters via a captured memset node
    void* cellcnt_ptr = nullptr;
    cudaGetSymbolAddress(&cellcnt_ptr, g_cellcnt);
    cudaMemsetAsync(cellcnt_ptr, 0, NCELL * sizeof(int));

    build_pts<<<(Kn + 255) / 256, 256>>>(pos, pnm, W1, asrc1, adst1);
    nbr_search<<<(Kn * 32 + 127) / 128, 128>>>();

    // ---- GAT layer 1 ----
    feat1<<<Kn / FNODES, F>>>(W1);
    aggregate<false><<<(Kn * 32 + 255) / 256, 256>>>(b1, nullptr, nullptr, nullptr);

    // ---- GAT layer 2 (scores fused into gemm2 epilogue) ----
    gemm2<<<dim3(F / BN, (Kn + BM - 1) / BM), 256>>>(W2, asrc2, adst2);
    aggregate<true><<<(Mp * 32 + 255) / 256, 256>>>(b2, fw, fb, out);
}

// round 16
// speedup vs baseline: 1.2716x; 1.2716x over previous
#include <cuda_runtime.h>

#define Kn 6000
#define Np 3000
#define Mp 3000
#define F 256
#define H 4
#define HID 64
#define MAXNB 32
#define R2 0.0025f
#define SLOPE 0.2f

#define CELLS 20
#define NCELL (CELLS * CELLS * CELLS)
#define CSINV 19.8019801980198f   /* 1 / 0.0505 ; cell > max accepted pair dist */

#define FNODES 8                  /* nodes per feat1 block */

// ---- device scratch (no dynamic allocation allowed) ----
__device__ float4 g_pts[Kn];
__device__ int    g_cellid[Kn];
__device__ int    g_cellcnt[NCELL];
__device__ int    g_cellstart[NCELL + 1];
__device__ int    g_cellpts[Kn];
__device__ float  g_w1as[H * 3];   // per-head W1^T @ asrc1  (3-vectors)
__device__ float  g_w1ad[H * 3];   // per-head W1^T @ adst1
__device__ int    g_nbr[Kn * MAXNB];
__device__ int    g_cnt[Kn];
__device__ float  g_h[Kn * F];
__device__ float  g_x[Kn * F];
__device__ float  g_es[Kn * H];
__device__ float  g_ed[Kn * H];

// ---- packed f32x2 helpers (bit-identical rn fp32 per lane, 2x FMA pipe) ----
__device__ __forceinline__ unsigned long long pack2(float lo, float hi) {
    unsigned long long r;
    asm("mov.b64 %0, {%1, %2};" : "=l"(r) : "f"(lo), "f"(hi));
    return r;
}
__device__ __forceinline__ void unpack2(unsigned long long v, float& lo, float& hi) {
    asm("mov.b64 {%0, %1}, %2;" : "=f"(lo), "=f"(hi) : "l"(v));
}
__device__ __forceinline__ void ffma2(unsigned long long& acc,
                                      unsigned long long a, unsigned long long b) {
    asm("fma.rn.f32x2 %0, %1, %2, %0;" : "+l"(acc) : "l"(a), "l"(b));
}
__device__ __forceinline__ void fadd2(unsigned long long& acc, unsigned long long o) {
    asm("add.rn.f32x2 %0, %0, %1;" : "+l"(acc) : "l"(o));
}

// ---------------------------------------------------------------------------
// 1. pack points {x,y,z,|p|^2}, compute cell id, count per cell.
//    Side job (block 0, 24 threads): per-head score 3-vectors W1^T @ a.
//    (g_cellcnt zeroed by a captured cudaMemsetAsync before this launch)
// ---------------------------------------------------------------------------
__global__ void build_pts(const float* __restrict__ pos,
                          const float* __restrict__ pnm,
                          const float* __restrict__ W1,
                          const float* __restrict__ asrc,
                          const float* __restrict__ adst) {
    if (blockIdx.x == 0 && threadIdx.x < 24) {
        int t = threadIdx.x;
        int sd = t & 1, d = (t >> 1) % 3, h = t / 6;
        const float* a = sd ? adst : asrc;
        float s = 0.f;
#pragma unroll 8
        for (int c = 0; c < HID; c++)
            s += W1[d * F + h * HID + c] * a[h * HID + c];
        (sd ? g_w1ad : g_w1as)[h * 3 + d] = s;
    }
    int i = blockIdx.x * blockDim.x + threadIdx.x;
    if (i >= Kn) return;
    float x, y, z;
    if (i < Np) { x = pos[i];     y = pos[Np + i];  z = pos[2 * Np + i]; }
    else        { int j = i - Np; x = pnm[j];       y = pnm[Mp + j];  z = pnm[2 * Mp + j]; }
    float sq = x * x + y * y + z * z;
    g_pts[i] = make_float4(x, y, z, sq);
    int cx = min(CELLS - 1, max(0, (int)(x * CSINV)));
    int cy = min(CELLS - 1, max(0, (int)(y * CSINV)));
    int cz = min(CELLS - 1, max(0, (int)(z * CSINV)));
    int cell = (cz * CELLS + cy) * CELLS + cx;
    g_cellid[i] = cell;
    atomicAdd(&g_cellcnt[cell], 1);
}

// ---------------------------------------------------------------------------
// 2. fused exclusive scan (shfl-based, 2 barriers) + scatter.
//    One block, 1024 threads; fill cursors live in shared memory.
// ---------------------------------------------------------------------------
__global__ void scan_scatter() {
    __shared__ int sfill[NCELL];   // 32 KB fill cursors
    __shared__ int wsum[32];
    int t = threadIdx.x;
    int lane = t & 31, warp = t >> 5;

    int loc[8], s = 0;
#pragma unroll
    for (int q = 0; q < 8; q++) {
        int idx = t * 8 + q;
        loc[q] = s;
        if (idx < NCELL) s += g_cellcnt[idx];
    }
    // inclusive warp scan of per-thread sums
    int incl = s;
#pragma unroll
    for (int off = 1; off < 32; off <<= 1) {
        int v = __shfl_up_sync(0xffffffffu, incl, off);
        if (lane >= off) incl += v;
    }
    if (lane == 31) wsum[warp] = incl;
    __syncthreads();
    if (warp == 0) {
        int v = wsum[lane];
        int w = v;
#pragma unroll
        for (int off = 1; off < 32; off <<= 1) {
            int u = __shfl_up_sync(0xffffffffu, w, off);
            if (lane >= off) w += u;
        }
        wsum[lane] = w;
    }
    __syncthreads();
    int base = ((warp > 0) ? wsum[warp - 1] : 0) + incl - s;  // exclusive thread base
#pragma unroll
    for (int q = 0; q < 8; q++) {
        int idx = t * 8 + q;
        if (idx < NCELL) {
            int st = base + loc[q];
            g_cellstart[idx] = st;
            sfill[idx] = st;
        }
    }
    if (t == 1023) g_cellstart[NCELL] = wsum[31];
    __syncthreads();

    // scatter (~6 points per thread); order randomized but nbr rank-sort fixes it
    for (int i = t; i < Kn; i += 1024) {
        int c = g_cellid[i];
        int p = atomicAdd(&sfill[c], 1);
        g_cellpts[p] = i;
    }
}

// ---------------------------------------------------------------------------
// 3. warp-per-node radius search (R9 span-ballot version, measured 11 us).
//    3 x-adjacent cells are contiguous in g_cellpts -> 9 spans per node.
//    Ballot-compacted hits, then rank-sorted ascending (indices unique)
//    -> identical edge list + order as the dense scan.
// ---------------------------------------------------------------------------
__global__ void nbr_search() {
    __shared__ int buf[4][MAXNB];
    int wslot = threadIdx.x >> 5;
    int lane  = threadIdx.x & 31;
    int i     = (blockIdx.x * blockDim.x + threadIdx.x) >> 5;
    if (i >= Kn) return;
    float4 pi = g_pts[i];
    int cx = min(CELLS - 1, max(0, (int)(pi.x * CSINV)));
    int cy = min(CELLS - 1, max(0, (int)(pi.y * CSINV)));
    int cz = min(CELLS - 1, max(0, (int)(pi.z * CSINV)));
    int x0 = max(cx - 1, 0), x1 = min(cx + 1, CELLS - 1);
    int* nb = buf[wslot];
    int cnt = 0;
    for (int dz = -1; dz <= 1; dz++) {
        int z = cz + dz;
        if ((unsigned)z >= CELLS) continue;
        for (int dy = -1; dy <= 1; dy++) {
            int y = cy + dy;
            if ((unsigned)y >= CELLS) continue;
            int rowbase = (z * CELLS + y) * CELLS;
            int s = g_cellstart[rowbase + x0];
            int e = g_cellstart[rowbase + x1 + 1];
            for (int t0 = s; t0 < e; t0 += 32) {
                int t = t0 + lane;
                bool ok = false;
                int j = -1;
                if (t < e) {
                    j = g_cellpts[t];
                    float4 pj = g_pts[j];
                    float dot = pi.x * pj.x + pi.y * pj.y + pi.z * pj.z;
                    float d2  = (pi.w + pj.w) - 2.0f * dot;   // identical to reference
                    ok = (d2 < R2);
                }
                unsigned m = __ballot_sync(0xffffffffu, ok);
                if (ok) {
                    int p = cnt + __popc(m & ((1u << lane) - 1u));
                    if (p < MAXNB) nb[p] = j;
                }
                cnt += __popc(m);
                if (cnt > MAXNB) cnt = MAXNB;
            }
        }
    }
    __syncwarp();
    // rank sort: indices unique -> rank = #{u < v} is a permutation
    int v = (lane < cnt) ? nb[lane] : 0x7fffffff;
    int rank = 0;
#pragma unroll
    for (int k = 0; k < 32; k++) {
        int u = __shfl_sync(0xffffffffu, v, k);
        rank += (u < v);
    }
    if (lane < cnt) g_nbr[i * MAXNB + rank] = v;
    if (lane == 0)  g_cnt[i] = cnt;
}

// ---------------------------------------------------------------------------
// 4. h1 = pts @ W1; scores via precomputed 3-vectors: es = p . (W1^T asrc).
//    No reductions, no barriers. FNODES nodes per block.
// ---------------------------------------------------------------------------
__global__ void feat1(const float* __restrict__ W1) {
    int c = threadIdx.x;
    float w0 = W1[c], w1 = W1[F + c], w2 = W1[2 * F + c];
    int i0 = blockIdx.x * FNODES;
#pragma unroll
    for (int n = 0; n < FNODES; n++) {
        int i = i0 + n;
        float4 p = g_pts[i];                      // broadcast load
        g_h[i * F + c] = p.x * w0 + p.y * w1 + p.z * w2;
    }
    if (c < 2 * FNODES * H) {                     // 64 threads: sd, node, head
        int sd = c >> 5, idx = c & 31;
        int n = idx >> 2, h = idx & 3;
        float4 p = g_pts[i0 + n];
        const float* wa = (sd ? g_w1ad : g_w1as) + h * 3;
        float e = p.x * wa[0] + p.y * wa[1] + p.z * wa[2];
        (sd ? g_ed : g_es)[(i0 + n) * H + h] = e;
    }
}

// ---------------------------------------------------------------------------
// 5. sparse GAT softmax + aggregation; warp per node.
//    FINAL: only rows [Np, Kn) are ever used -> fuse fc and skip the rest.
// ---------------------------------------------------------------------------
template<bool FINAL>
__global__ void aggregate(const float* __restrict__ bias,
                          const float* __restrict__ fw,
                          const float* __restrict__ fb,
                          float* __restrict__ out) {
    int wi   = (blockIdx.x * blockDim.x + threadIdx.x) >> 5;
    int lane = threadIdx.x & 31;
    if (wi >= (FINAL ? Mp : Kn)) return;
    int node = FINAL ? (Np + wi) : wi;
    int cnt  = g_cnt[node];

    float e[H];
    int nb = 0;
    if (lane < cnt) {
        nb = g_nbr[node * MAXNB + lane];
#pragma unroll
        for (int h = 0; h < H; h++) {
            float v = g_ed[node * H + h] + g_es[nb * H + h];
            e[h] = (v >= 0.f) ? v : SLOPE * v;
        }
    } else {
#pragma unroll
        for (int h = 0; h < H; h++) e[h] = -1e30f;
    }

    float alpha[H];
#pragma unroll
    for (int h = 0; h < H; h++) {
        float m = e[h];
#pragma unroll
        for (int off = 16; off; off >>= 1)
            m = fmaxf(m, __shfl_xor_sync(0xffffffffu, m, off));
        float a = (lane < cnt) ? expf(e[h] - m) : 0.f;
        float s = a;
#pragma unroll
        for (int off = 16; off; off >>= 1)
            s += __shfl_xor_sync(0xffffffffu, s, off);
        alpha[h] = a / s;
    }

    float acc[8] = {0.f, 0.f, 0.f, 0.f, 0.f, 0.f, 0.f, 0.f};
    for (int j = 0; j < cnt; j++) {
        int   nj = __shfl_sync(0xffffffffu, nb, j);
        float aw[H];
#pragma unroll
        for (int h = 0; h < H; h++) aw[h] = __shfl_sync(0xffffffffu, alpha[h], j);
        const float* hr = g_h + nj * F;
#pragma unroll
        for (int r = 0; r < 8; r++)
            acc[r] += aw[r >> 1] * hr[lane + 32 * r];
    }

    float f0 = 0.f, f1 = 0.f;
#pragma unroll
    for (int r = 0; r < 8; r++) {
        int c = lane + 32 * r;
        float v = acc[r] + bias[c];
        v = (v > 0.f) ? v : 0.f;
        if (!FINAL) {
            g_x[node * F + c] = v;
        } else {
            f0 += v * fw[c * 2];
            f1 += v * fw[c * 2 + 1];
        }
    }
    if (FINAL) {
#pragma unroll
        for (int off = 16; off; off >>= 1) {
            f0 += __shfl_xor_sync(0xffffffffu, f0, off);
            f1 += __shfl_xor_sync(0xffffffffu, f1, off);
        }
        if (lane == 0) {
            out[wi * 2]     = f0 + fb[0];
            out[wi * 2 + 1] = f1 + fb[1];
        }
    }
}

// ---------------------------------------------------------------------------
// 6. h2 = x1 @ W2 — BM=64 x BN=64, 256 threads, SPLIT-K=2 (R13, kept).
// ---------------------------------------------------------------------------
#define BM 64
#define BN 64
#define BKT 32
__global__ void __launch_bounds__(256) gemm2(const float* __restrict__ W,
                                             const float* __restrict__ asrc,
                                             const float* __restrict__ adst) {
    __shared__ __align__(16) float smem_buf[BKT * BM + BKT * BN];  // 16 KB
    float* As = smem_buf;                 // As[k][m] = As[k*BM+m], transposed
    float* Bs = smem_buf + BKT * BM;      // Bs[k][n] = Bs[k*BN+n]
    int tid = threadIdx.x;
    int kg = tid >> 7;                    // split-K group: 0 or 1
    int wg_tid = tid & 127;
    int row0 = blockIdx.y * BM, col0 = blockIdx.x * BN;
    int tx = wg_tid & 15, ty = wg_tid >> 4;   // tx: n-quad, ty: m-group of 8
    unsigned long long acc[4][4];             // acc[mpair][n]
#pragma unroll
    for (int mp = 0; mp < 4; mp++)
#pragma unroll
        for (int n = 0; n < 4; n++) acc[mp][n] = 0ull;

    for (int kk = 0; kk < F; kk += BKT) {
#pragma unroll
        for (int it = 0; it < 2; it++) {
            int idx = tid + it * 256;
            int m = idx & 63, q = idx >> 6;       // q in 0..7
            int gr = row0 + m;
            float4 v = make_float4(0.f, 0.f, 0.f, 0.f);
            if (gr < Kn) v = *(const float4*)&g_x[gr * F + kk + q * 4];
            As[(q * 4 + 0) * BM + m] = v.x; As[(q * 4 + 1) * BM + m] = v.y;
            As[(q * 4 + 2) * BM + m] = v.z; As[(q * 4 + 3) * BM + m] = v.w;
        }
#pragma unroll
        for (int it = 0; it < 2; it++) {
            int idx = tid + it * 256;
            int k = idx >> 4, n4 = idx & 15;
            *(float4*)&Bs[k * BN + n4 * 4] =
                *(const float4*)&W[(kk + k) * F + col0 + n4 * 4];
        }
        __syncthreads();
#pragma unroll
        for (int k = 0; k < 16; k++) {
            int ks = kg * 16 + k;                 // this group's k within tile
            float4 b = *(const float4*)&Bs[ks * BN + tx * 4];
            unsigned long long bd[4];
            bd[0] = pack2(b.x, b.x); bd[1] = pack2(b.y, b.y);
            bd[2] = pack2(b.z, b.z); bd[3] = pack2(b.w, b.w);
            float4 a0 = *(const float4*)&As[ks * BM + ty * 8];
            float4 a1 = *(const float4*)&As[ks * BM + ty * 8 + 4];
            unsigned long long ap[4];
            ap[0] = pack2(a0.x, a0.y); ap[1] = pack2(a0.z, a0.w);
            ap[2] = pack2(a1.x, a1.y); ap[3] = pack2(a1.z, a1.w);
#pragma unroll
            for (int mp = 0; mp < 4; mp++)
#pragma unroll
                for (int n = 0; n < 4; n++) ffma2(acc[mp][n], ap[mp], bd[n]);
        }
        __syncthreads();
    }

    // split-K reduction: group1 -> smem, group0 adds (fixed order, deterministic)
    unsigned long long* red = (unsigned long long*)smem_buf;
    if (kg == 1) {
#pragma unroll
        for (int idx = 0; idx < 16; idx++)
            red[idx * 128 + wg_tid] = acc[idx >> 2][idx & 3];
    }
    __syncthreads();
    if (kg != 0) return;
#pragma unroll
    for (int idx = 0; idx < 16; idx++)
        fadd2(acc[idx >> 2][idx & 3], red[idx * 128 + wg_tid]);

    // epilogue (group0 only): unpack, store h2, fused es/ed for this head
    float as_[4], ad_[4];
#pragma unroll
    for (int n = 0; n < 4; n++) {
        as_[n] = asrc[col0 + tx * 4 + n];
        ad_[n] = adst[col0 + tx * 4 + n];
    }
    int hidx = col0 >> 6;
#pragma unroll
    for (int mp = 0; mp < 4; mp++) {
        float c0[4], c1[4];
#pragma unroll
        for (int n = 0; n < 4; n++) unpack2(acc[mp][n], c0[n], c1[n]);
#pragma unroll
        for (int half = 0; half < 2; half++) {
            float* c = half ? c1 : c0;
            int gr = row0 + ty * 8 + mp * 2 + half;
            float s = c[0] * as_[0] + c[1] * as_[1] + c[2] * as_[2] + c[3] * as_[3];
            float d = c[0] * ad_[0] + c[1] * ad_[1] + c[2] * ad_[2] + c[3] * ad_[3];
#pragma unroll
            for (int off = 8; off; off >>= 1) {
                s += __shfl_xor_sync(0xffffffffu, s, off);
                d += __shfl_xor_sync(0xffffffffu, d, off);
            }
            if (gr < Kn) {
                *(float4*)&g_h[gr * F + col0 + tx * 4] =
                    make_float4(c[0], c[1], c[2], c[3]);
                if (tx == 0) {
                    g_es[gr * H + hidx] = s;
                    g_ed[gr * H + hidx] = d;
                }
            }
        }
    }
}

// ---------------------------------------------------------------------------
extern "C" void kernel_launch(void* const* d_in, const int* in_sizes, int n_in,
                              void* d_out, int out_size) {
    const float* pos   = (const float*)d_in[0];
    const float* pnm   = (const float*)d_in[1];
    const float* W1    = (const float*)d_in[2];
    const float* asrc1 = (const float*)d_in[3];
    const float* adst1 = (const float*)d_in[4];
    const float* b1    = (const float*)d_in[5];
    const float* W2    = (const float*)d_in[6];
    const float* asrc2 = (const float*)d_in[7];
    const float* adst2 = (const float*)d_in[8];
    const float* b2    = (const float*)d_in[9];
    const float* fw    = (const float*)d_in[10];
    const float* fb    = (const float*)d_in[11];
    float* out = (float*)d_out;

    // zero the cell counters via a captured memset node
    void* cellcnt_ptr = nullptr;
    cudaGetSymbolAddress(&cellcnt_ptr, g_cellcnt);
    cudaMemsetAsync(cellcnt_ptr, 0, NCELL * sizeof(int));

    build_pts<<<(Kn + 255) / 256, 256>>>(pos, pnm, W1, asrc1, adst1);
    scan_scatter<<<1, 1024>>>();
    nbr_search<<<(Kn * 32 + 127) / 128, 128>>>();

    // ---- GAT layer 1 ----
    feat1<<<Kn / FNODES, F>>>(W1);
    aggregate<false><<<(Kn * 32 + 255) / 256, 256>>>(b1, nullptr, nullptr, nullptr);

    // ---- GAT layer 2 (scores fused into gemm2 epilogue) ----
    gemm2<<<dim3(F / BN, (Kn + BM - 1) / BM), 256>>>(W2, asrc2, adst2);
    aggregate<true><<<(Mp * 32 + 255) / 256, 256>>>(b2, fw, fb, out);
}